// round 16
// baseline (speedup 1.0000x reference)
#include <cuda_runtime.h>
#include <cuda_fp16.h>
#include <math.h>
#include <stdint.h>

#define NB 32768
#define NN 1024
#define NM 64

// smem map: CTA = 64 rows, 2 CTAs/SM
#define SM_A   0                 // 2 levels x 16384 (A frags, fp16)
#define SM_B   32768             // 2 x 32768 (B unit double buffer)
#define SM_CB  98304             // 64 floats
#define SM_RM  98560             // 4 x 64 floats (raw) -> [0..63] final rowmax
#define SM_TOT 99584

__device__ __align__(16) unsigned char g_Wb[16 * 32768];  // 512 KB frag-linear B
__device__ __align__(16) float g_logprior[NN];
__device__ __align__(16) float g_inv_sd[NM];

__device__ __forceinline__ uint32_t smem_u32(const void* p) {
    return (uint32_t)__cvta_generic_to_shared(p);
}
__device__ __forceinline__ void cp16(uint32_t s, const void* g) {
    asm volatile("cp.async.cg.shared.global [%0], [%1], 16;" :: "r"(s), "l"(g) : "memory");
}
__device__ __forceinline__ uint4 lds128(uint32_t a) {
    uint4 v;
    asm volatile("ld.shared.v4.b32 {%0,%1,%2,%3}, [%4];"
                 : "=r"(v.x), "=r"(v.y), "=r"(v.z), "=r"(v.w) : "r"(a));
    return v;
}
__device__ __forceinline__ uint2 lds64(uint32_t a) {
    uint2 v;
    asm volatile("ld.shared.v2.b32 {%0,%1}, [%2];" : "=r"(v.x), "=r"(v.y) : "r"(a));
    return v;
}
__device__ __forceinline__ void sts128(uint32_t a, uint32_t x, uint32_t y, uint32_t z, uint32_t w) {
    asm volatile("st.shared.v4.b32 [%0], {%1,%2,%3,%4};" :: "r"(a), "r"(x), "r"(y), "r"(z), "r"(w) : "memory");
}
__device__ __forceinline__ void mma16816(float* c, uint4 a, uint2 b) {
    asm volatile("mma.sync.aligned.m16n8k16.row.col.f32.f16.f16.f32 "
                 "{%0,%1,%2,%3}, {%4,%5,%6,%7}, {%8,%9}, {%0,%1,%2,%3};"
                 : "+f"(c[0]), "+f"(c[1]), "+f"(c[2]), "+f"(c[3])
                 : "r"(a.x), "r"(a.y), "r"(a.z), "r"(a.w), "r"(b.x), "r"(b.y));
}
__device__ __forceinline__ void split2(float2 v, uint32_t& u0, uint32_t& u1) {
    __half2 h0 = __floats2half2_rn(v.x, v.y);
    float rx = v.x - __low2float(h0);
    float ry = v.y - __high2float(h0);
    __half2 h1 = __floats2half2_rn(rx, ry);
    u0 = *(uint32_t*)&h0; u1 = *(uint32_t*)&h1;
}
__device__ __forceinline__ unsigned short hlvl(float w, int lvl) {
    __half h0 = __float2half_rn(w);
    if (lvl == 0) return *(unsigned short*)&h0;
    float r = w - __half2float(h0);
    __half h1 = __float2half_rn(r);
    return *(unsigned short*)&h1;
}

// ---- prep: logprior + inv_sd + frag-linear fp16 B units ----
__global__ void prep_all(const float* __restrict__ C, const float* __restrict__ sd,
                         const float* __restrict__ lm) {
    __shared__ float red[256];
    const int t = threadIdx.x;
    if (blockIdx.x == 0) {
        if (t < NM) g_inv_sd[t] = 1.0f / sd[t];
        float mx = -1e30f;
        for (int i = t; i < NN; i += 256) mx = fmaxf(mx, lm[i]);
        red[t] = mx; __syncthreads();
        for (int s = 128; s > 0; s >>= 1) {
            if (t < s) red[t] = fmaxf(red[t], red[t + s]);
            __syncthreads();
        }
        mx = red[0]; __syncthreads();
        float sum = 0.f;
        for (int i = t; i < NN; i += 256) sum += expf(lm[i] - mx);
        red[t] = sum; __syncthreads();
        for (int s = 128; s > 0; s >>= 1) {
            if (t < s) red[t] += red[t + s];
            __syncthreads();
        }
        float lse = mx + logf(red[0]);
        for (int i = t; i < NN; i += 256) g_logprior[i] = lm[i] - lse;
    }
    int idx = blockIdx.x * 256 + t;
    if (idx >= 16 * 4096) return;
    int lane = idx & 31;
    int nt   = (idx >> 5) & 15;
    int ks   = (idx >> 9) & 7;
    int u    = idx >> 12;                    // unit 0..15
    int chunk = u >> 1, lvl = u & 1;
    int col = chunk * 128 + nt * 8 + (lane >> 2);
    int k0  = ks * 16 + 2 * (lane & 3);
    float w[4];
    #pragma unroll
    for (int q = 0; q < 4; q++) {
        int k = k0 + (q >> 1) * 8 + (q & 1);
        if (k < NM) w[q] = C[(size_t)col * NM + k];
        else { float c = C[(size_t)col * NM + (k - NM)]; w[q] = -0.5f * c * c; }
    }
    uint32_t r0 = (uint32_t)hlvl(w[0], lvl) | ((uint32_t)hlvl(w[1], lvl) << 16);
    uint32_t r1 = (uint32_t)hlvl(w[2], lvl) | ((uint32_t)hlvl(w[3], lvl) << 16);
    ((uint2*)g_Wb)[idx] = make_uint2(r0, r1);
}

// ---- fused: HMMA GEMM + logits + in-block softmax (2 CTAs/SM overlap) ----
__global__ __launch_bounds__(256, 2)
void gemm_fused(const float* __restrict__ samples, const float* __restrict__ mask,
                float* __restrict__ out) {
    extern __shared__ unsigned char smem[];
    const uint32_t sb = smem_u32(smem);
    float* sCb  = (float*)(smem + SM_CB);
    float* sRm  = (float*)(smem + SM_RM);
    float* Ubuf = (float*)(smem + SM_B + 32768);
    const int t = threadIdx.x, warp = t >> 5, lane = t & 31;
    const int r0 = blockIdx.x * 64;
    const int wm = warp & 1, wn = warp >> 1;
    float* scratch = out + (size_t)NB * NN;

    {
        const char* src = (const char*)g_Wb + (size_t)t * 16;
        uint32_t dst = sb + SM_B + (uint32_t)t * 16;
        #pragma unroll
        for (int i = 0; i < 8; i++) cp16(dst + i * 4096, src + (size_t)i * 4096);
        asm volatile("cp.async.commit_group;" ::: "memory");
    }

    {
        int row = t >> 2, p = t & 3;
        const float4* M4 = (const float4*)(mask    + (size_t)(r0 + row) * NM);
        const float4* S4 = (const float4*)(samples + (size_t)(r0 + row) * NM);
        float cbp = 0.f;
        int hh = p & 1;
        float4* Ud = (float4*)(Ubuf + row * 128 + (p >> 1) * 64 + hh * 32);
        #pragma unroll
        for (int i = 0; i < 8; i++) {
            int q4 = hh * 8 + i;
            float4 mv = M4[q4];
            float4 iv = *(const float4*)(g_inv_sd + q4 * 4);
            float a = mv.x * iv.x, b = mv.y * iv.y, c = mv.z * iv.z, d = mv.w * iv.w;
            float4 qv = make_float4(a * a, b * b, c * c, d * d);
            if (p < 2) {
                float4 sv = S4[q4];
                float4 uv = make_float4(qv.x * sv.x, qv.y * sv.y, qv.z * sv.z, qv.w * sv.w);
                cbp += uv.x * sv.x + uv.y * sv.y + uv.z * sv.z + uv.w * sv.w;
                Ud[i] = uv;
            } else {
                Ud[i] = qv;
            }
        }
        cbp += __shfl_down_sync(0xffffffffu, cbp, 1);
        if (p == 0) sCb[row] = -0.5f * cbp;
    }
    __syncthreads();

    {
        const int mt = warp & 3;
        const int ksb = (warp >> 2) * 4;
        const int rA = mt * 16 + (lane >> 2), rB = rA + 8;
        const float2* U2 = (const float2*)Ubuf;
        #pragma unroll
        for (int kk = 0; kk < 4; kk++) {
            int ks = ksb + kk;
            int k0 = ks * 16 + 2 * (lane & 3);
            float2 A0 = U2[rA * 64 + (k0 >> 1)];
            float2 A1 = U2[rB * 64 + (k0 >> 1)];
            float2 A2 = U2[rA * 64 + ((k0 + 8) >> 1)];
            float2 A3 = U2[rB * 64 + ((k0 + 8) >> 1)];
            uint32_t L0[4], L1[4];
            split2(A0, L0[0], L1[0]);
            split2(A1, L0[1], L1[1]);
            split2(A2, L0[2], L1[2]);
            split2(A3, L0[3], L1[3]);
            uint32_t off = sb + SM_A + (uint32_t)(((ks * 4 + mt) * 32 + lane) * 16);
            sts128(off,          L0[0], L0[1], L0[2], L0[3]);
            sts128(off + 16384u, L1[0], L1[1], L1[2], L1[3]);
        }
    }
    __syncthreads();

    float cbA[2], cbB[2];
    #pragma unroll
    for (int mi = 0; mi < 2; mi++) {
        cbA[mi] = sCb[wm * 32 + mi * 16 + (lane >> 2)];
        cbB[mi] = sCb[wm * 32 + mi * 16 + (lane >> 2) + 8];
    }
    float acc[2][4][4];
    #pragma unroll
    for (int mi = 0; mi < 2; mi++)
        #pragma unroll
        for (int j = 0; j < 4; j++)
            #pragma unroll
            for (int q = 0; q < 4; q++) acc[mi][j][q] = 0.f;
    float rmax[4];
    #pragma unroll
    for (int i = 0; i < 4; i++) rmax[i] = -1e30f;

    #pragma unroll 1
    for (int u = 0; u < 16; u++) {
        if (u + 1 < 16) {
            const char* src = (const char*)g_Wb + (size_t)(u + 1) * 32768 + (size_t)t * 16;
            uint32_t dst = sb + SM_B + (uint32_t)((u + 1) & 1) * 32768u + (uint32_t)t * 16;
            #pragma unroll
            for (int i = 0; i < 8; i++) cp16(dst + i * 4096, src + (size_t)i * 4096);
            asm volatile("cp.async.commit_group;" ::: "memory");
            asm volatile("cp.async.wait_group 1;" ::: "memory");
        } else {
            asm volatile("cp.async.wait_group 0;" ::: "memory");
        }
        __syncthreads();

        const uint32_t bBase = sb + SM_B + (uint32_t)(u & 1) * 32768u
                             + (uint32_t)(((wn * 4) * 32 + lane) * 8);
        #pragma unroll
        for (int ks = 0; ks < 8; ks++) {
            uint2 bf[4];
            #pragma unroll
            for (int j = 0; j < 4; j++)
                bf[j] = lds64(bBase + (uint32_t)((ks * 16 + j) * 256));
            #pragma unroll
            for (int lvl = 0; lvl < 2; lvl++) {
                uint4 af0 = lds128(sb + SM_A + (uint32_t)lvl * 16384u
                                   + (uint32_t)(((ks * 4 + wm * 2) * 32 + lane) * 16));
                uint4 af1 = lds128(sb + SM_A + (uint32_t)lvl * 16384u
                                   + (uint32_t)(((ks * 4 + wm * 2 + 1) * 32 + lane) * 16));
                #pragma unroll
                for (int j = 0; j < 4; j++) {
                    mma16816(acc[0][j], af0, bf[j]);
                    mma16816(acc[1][j], af1, bf[j]);
                }
            }
        }
        __syncthreads();

        if (u & 1) {
            const int chunk = u >> 1;
            const int colBase = chunk * 128 + wn * 32 + 2 * (lane & 3);
            #pragma unroll
            for (int j = 0; j < 4; j++) {
                const float2 lp = *(const float2*)(g_logprior + colBase + j * 8);
                #pragma unroll
                for (int mi = 0; mi < 2; mi++) {
                    const int rA = wm * 32 + mi * 16 + (lane >> 2);
                    float l00 = lp.x + fminf(acc[mi][j][0] + cbA[mi], 0.f);
                    float l01 = lp.y + fminf(acc[mi][j][1] + cbA[mi], 0.f);
                    float l10 = lp.x + fminf(acc[mi][j][2] + cbB[mi], 0.f);
                    float l11 = lp.y + fminf(acc[mi][j][3] + cbB[mi], 0.f);
                    rmax[mi * 2]     = fmaxf(rmax[mi * 2],     fmaxf(l00, l01));
                    rmax[mi * 2 + 1] = fmaxf(rmax[mi * 2 + 1], fmaxf(l10, l11));
                    *(float2*)(scratch + (size_t)(r0 + rA) * NN + colBase + j * 8)
                        = make_float2(l00, l01);
                    *(float2*)(scratch + (size_t)(r0 + rA + 8) * NN + colBase + j * 8)
                        = make_float2(l10, l11);
                    acc[mi][j][0] = 0.f; acc[mi][j][1] = 0.f;
                    acc[mi][j][2] = 0.f; acc[mi][j][3] = 0.f;
                }
            }
        }
    }

    // rowmax: quad-lanes -> wn slices -> final per-row max in sRm[0..63]
    #pragma unroll
    for (int i = 0; i < 4; i++) {
        rmax[i] = fmaxf(rmax[i], __shfl_xor_sync(0xffffffffu, rmax[i], 1));
        rmax[i] = fmaxf(rmax[i], __shfl_xor_sync(0xffffffffu, rmax[i], 2));
    }
    if ((lane & 3) == 0) {
        #pragma unroll
        for (int mi = 0; mi < 2; mi++) {
            int rA = wm * 32 + mi * 16 + (lane >> 2);
            sRm[wn * 64 + rA]     = rmax[mi * 2];
            sRm[wn * 64 + rA + 8] = rmax[mi * 2 + 1];
        }
    }
    __syncthreads();
    if (t < 64) {
        sRm[t] = fmaxf(fmaxf(sRm[t], sRm[64 + t]),
                       fmaxf(sRm[128 + t], sRm[192 + t]));
    }
    __syncthreads();   // also makes this block's scratch writes visible block-wide

    // ---- in-block softmax: 8 rows/warp, 2 rows in flight per iteration ----
    const float LZ = __logf(1e-20f);
    #pragma unroll 1
    for (int rp = 0; rp < 4; rp++) {
        const int rowA = warp * 8 + rp * 2;
        const int rowB = rowA + 1;
        const float mxA = sRm[rowA], mxB = sRm[rowB];
        const float4* LA = (const float4*)(scratch + (size_t)(r0 + rowA) * NN);
        const float4* LB = (const float4*)(scratch + (size_t)(r0 + rowB) * NN);
        float4 xa[8], xb[8];
        #pragma unroll
        for (int i = 0; i < 8; i++) { xa[i] = LA[lane + 32 * i]; xb[i] = LB[lane + 32 * i]; }
        float sA = 0.f, sB = 0.f;
        #pragma unroll
        for (int i = 0; i < 8; i++) {
            float4 v = xa[i];
            float p0 = 0.f, p1 = 0.f, p2 = 0.f, p3 = 0.f;
            float d0 = v.x - mxA, d1 = v.y - mxA, d2 = v.z - mxA, d3 = v.w - mxA;
            if (d0 > -3.4f) { float e = __expf(d0); p0 = (e > 0.05f) ? e : 0.f; }
            if (d1 > -3.4f) { float e = __expf(d1); p1 = (e > 0.05f) ? e : 0.f; }
            if (d2 > -3.4f) { float e = __expf(d2); p2 = (e > 0.05f) ? e : 0.f; }
            if (d3 > -3.4f) { float e = __expf(d3); p3 = (e > 0.05f) ? e : 0.f; }
            xa[i] = make_float4(p0, p1, p2, p3);
            sA += (p0 + p1) + (p2 + p3);
            v = xb[i];
            p0 = 0.f; p1 = 0.f; p2 = 0.f; p3 = 0.f;
            d0 = v.x - mxB; d1 = v.y - mxB; d2 = v.z - mxB; d3 = v.w - mxB;
            if (d0 > -3.4f) { float e = __expf(d0); p0 = (e > 0.05f) ? e : 0.f; }
            if (d1 > -3.4f) { float e = __expf(d1); p1 = (e > 0.05f) ? e : 0.f; }
            if (d2 > -3.4f) { float e = __expf(d2); p2 = (e > 0.05f) ? e : 0.f; }
            if (d3 > -3.4f) { float e = __expf(d3); p3 = (e > 0.05f) ? e : 0.f; }
            xb[i] = make_float4(p0, p1, p2, p3);
            sB += (p0 + p1) + (p2 + p3);
        }
        #pragma unroll
        for (int o = 16; o > 0; o >>= 1) {
            sA += __shfl_xor_sync(0xffffffffu, sA, o);
            sB += __shfl_xor_sync(0xffffffffu, sB, o);
        }
        const float invA = 1.0f / sA, invB = 1.0f / sB;
        float4* poA = (float4*)(out + (size_t)(r0 + rowA) * NN);
        float4* loA = (float4*)(scratch + (size_t)(r0 + rowA) * NN);
        float4* poB = (float4*)(out + (size_t)(r0 + rowB) * NN);
        float4* loB = (float4*)(scratch + (size_t)(r0 + rowB) * NN);
        #pragma unroll
        for (int i = 0; i < 8; i++) {
            float4 v = xa[i];
            float4 P = make_float4(v.x * invA, v.y * invA, v.z * invA, v.w * invA);
            float4 Lg;
            Lg.x = (v.x > 0.f) ? __logf(P.x + 1e-20f) : LZ;
            Lg.y = (v.y > 0.f) ? __logf(P.y + 1e-20f) : LZ;
            Lg.z = (v.z > 0.f) ? __logf(P.z + 1e-20f) : LZ;
            Lg.w = (v.w > 0.f) ? __logf(P.w + 1e-20f) : LZ;
            poA[lane + 32 * i] = P;
            loA[lane + 32 * i] = Lg;
            v = xb[i];
            P = make_float4(v.x * invB, v.y * invB, v.z * invB, v.w * invB);
            Lg.x = (v.x > 0.f) ? __logf(P.x + 1e-20f) : LZ;
            Lg.y = (v.y > 0.f) ? __logf(P.y + 1e-20f) : LZ;
            Lg.z = (v.z > 0.f) ? __logf(P.z + 1e-20f) : LZ;
            Lg.w = (v.w > 0.f) ? __logf(P.w + 1e-20f) : LZ;
            poB[lane + 32 * i] = P;
            loB[lane + 32 * i] = Lg;
        }
    }
}

extern "C" void kernel_launch(void* const* d_in, const int* in_sizes, int n_in,
                              void* d_out, int out_size) {
    const float* samples = (const float*)d_in[0];
    const float* mask    = (const float*)d_in[1];
    const float* cent    = (const float*)d_in[2];
    const float* sd      = (const float*)d_in[3];
    const float* lm      = (const float*)d_in[4];
    float* out = (float*)d_out;
    (void)in_sizes; (void)n_in; (void)out_size;

    cudaFuncSetAttribute(gemm_fused, cudaFuncAttributeMaxDynamicSharedMemorySize, SM_TOT);

    prep_all<<<256, 256>>>(cent, sd, lm);
    gemm_fused<<<NB / 64, 256, SM_TOT>>>(samples, mask, out);
}

// round 17
// speedup vs baseline: 1.0513x; 1.0513x over previous
#include <cuda_runtime.h>
#include <cuda_fp16.h>
#include <math.h>
#include <stdint.h>

#define NB 32768
#define NN 1024
#define NM 64
#define NGEMM 512                // producer blocks (64 rows each)
#define NSOFT 2048               // consumer blocks (16 rows each)

// smem map (gemm branch): CTA = 64 rows
#define SM_A   0                 // 2 levels x 16384 (A frags, fp16)
#define SM_B   32768             // 2 x 32768 (B unit double buffer)
#define SM_CB  98304             // 64 floats
#define SM_RM  98560             // 4 x 64 floats
#define SM_TOT 99584

__device__ __align__(16) unsigned char g_Wb[16 * 32768];  // 512 KB frag-linear B
__device__ __align__(16) float g_logprior[NN];
__device__ __align__(16) float g_inv_sd[NM];
__device__ float g_rowmax[NB];
__device__ int   g_flag[NGEMM];

__device__ __forceinline__ uint32_t smem_u32(const void* p) {
    return (uint32_t)__cvta_generic_to_shared(p);
}
__device__ __forceinline__ void cp16(uint32_t s, const void* g) {
    asm volatile("cp.async.cg.shared.global [%0], [%1], 16;" :: "r"(s), "l"(g) : "memory");
}
__device__ __forceinline__ uint4 lds128(uint32_t a) {
    uint4 v;
    asm volatile("ld.shared.v4.b32 {%0,%1,%2,%3}, [%4];"
                 : "=r"(v.x), "=r"(v.y), "=r"(v.z), "=r"(v.w) : "r"(a));
    return v;
}
__device__ __forceinline__ uint2 lds64(uint32_t a) {
    uint2 v;
    asm volatile("ld.shared.v2.b32 {%0,%1}, [%2];" : "=r"(v.x), "=r"(v.y) : "r"(a));
    return v;
}
__device__ __forceinline__ void sts128(uint32_t a, uint32_t x, uint32_t y, uint32_t z, uint32_t w) {
    asm volatile("st.shared.v4.b32 [%0], {%1,%2,%3,%4};" :: "r"(a), "r"(x), "r"(y), "r"(z), "r"(w) : "memory");
}
__device__ __forceinline__ void mma16816(float* c, uint4 a, uint2 b) {
    asm volatile("mma.sync.aligned.m16n8k16.row.col.f32.f16.f16.f32 "
                 "{%0,%1,%2,%3}, {%4,%5,%6,%7}, {%8,%9}, {%0,%1,%2,%3};"
                 : "+f"(c[0]), "+f"(c[1]), "+f"(c[2]), "+f"(c[3])
                 : "r"(a.x), "r"(a.y), "r"(a.z), "r"(a.w), "r"(b.x), "r"(b.y));
}
__device__ __forceinline__ void split2(float2 v, uint32_t& u0, uint32_t& u1) {
    __half2 h0 = __floats2half2_rn(v.x, v.y);
    float rx = v.x - __low2float(h0);
    float ry = v.y - __high2float(h0);
    __half2 h1 = __floats2half2_rn(rx, ry);
    u0 = *(uint32_t*)&h0; u1 = *(uint32_t*)&h1;
}
__device__ __forceinline__ unsigned short hlvl(float w, int lvl) {
    __half h0 = __float2half_rn(w);
    if (lvl == 0) return *(unsigned short*)&h0;
    float r = w - __half2float(h0);
    __half h1 = __float2half_rn(r);
    return *(unsigned short*)&h1;
}

// ---- prep: logprior + inv_sd + flag reset + frag-linear fp16 B units ----
__global__ void prep_all(const float* __restrict__ C, const float* __restrict__ sd,
                         const float* __restrict__ lm) {
    __shared__ float red[256];
    const int t = threadIdx.x;
    if (blockIdx.x == 0) {
        if (t < NM) g_inv_sd[t] = 1.0f / sd[t];
        float mx = -1e30f;
        for (int i = t; i < NN; i += 256) mx = fmaxf(mx, lm[i]);
        red[t] = mx; __syncthreads();
        for (int s = 128; s > 0; s >>= 1) {
            if (t < s) red[t] = fmaxf(red[t], red[t + s]);
            __syncthreads();
        }
        mx = red[0]; __syncthreads();
        float sum = 0.f;
        for (int i = t; i < NN; i += 256) sum += expf(lm[i] - mx);
        red[t] = sum; __syncthreads();
        for (int s = 128; s > 0; s >>= 1) {
            if (t < s) red[t] += red[t + s];
            __syncthreads();
        }
        float lse = mx + logf(red[0]);
        for (int i = t; i < NN; i += 256) g_logprior[i] = lm[i] - lse;
    }
    if (blockIdx.x == 1 && t < NGEMM / 2) {        // reset flags (graph replay safe)
        g_flag[t] = 0; g_flag[t + NGEMM / 2] = 0;
    }
    int idx = blockIdx.x * 256 + t;
    if (idx >= 16 * 4096) return;
    int lane = idx & 31;
    int nt   = (idx >> 5) & 15;
    int ks   = (idx >> 9) & 7;
    int u    = idx >> 12;                    // unit 0..15
    int chunk = u >> 1, lvl = u & 1;
    int col = chunk * 128 + nt * 8 + (lane >> 2);
    int k0  = ks * 16 + 2 * (lane & 3);
    float w[4];
    #pragma unroll
    for (int q = 0; q < 4; q++) {
        int k = k0 + (q >> 1) * 8 + (q & 1);
        if (k < NM) w[q] = C[(size_t)col * NM + k];
        else { float c = C[(size_t)col * NM + (k - NM)]; w[q] = -0.5f * c * c; }
    }
    uint32_t r0 = (uint32_t)hlvl(w[0], lvl) | ((uint32_t)hlvl(w[1], lvl) << 16);
    uint32_t r1 = (uint32_t)hlvl(w[2], lvl) | ((uint32_t)hlvl(w[3], lvl) << 16);
    ((uint2*)g_Wb)[idx] = make_uint2(r0, r1);
}

// ---- fused pipeline kernel: blocks 0..511 gemm, 512..2559 softmax (16 rows) ----
__global__ __launch_bounds__(256, 2)
void fused_pipe(const float* __restrict__ samples, const float* __restrict__ mask,
                float* __restrict__ out) {
    extern __shared__ unsigned char smem[];
    const int t = threadIdx.x, warp = t >> 5, lane = t & 31;
    float* scratch = out + (size_t)NB * NN;

    if (blockIdx.x < NGEMM) {
        // ================= GEMM branch (verbatim R11/R15) =================
        const uint32_t sb = smem_u32(smem);
        float* sCb  = (float*)(smem + SM_CB);
        float* sRm  = (float*)(smem + SM_RM);
        float* Ubuf = (float*)(smem + SM_B + 32768);
        const int r0 = blockIdx.x * 64;
        const int wm = warp & 1, wn = warp >> 1;

        {
            const char* src = (const char*)g_Wb + (size_t)t * 16;
            uint32_t dst = sb + SM_B + (uint32_t)t * 16;
            #pragma unroll
            for (int i = 0; i < 8; i++) cp16(dst + i * 4096, src + (size_t)i * 4096);
            asm volatile("cp.async.commit_group;" ::: "memory");
        }

        {
            int row = t >> 2, p = t & 3;
            const float4* M4 = (const float4*)(mask    + (size_t)(r0 + row) * NM);
            const float4* S4 = (const float4*)(samples + (size_t)(r0 + row) * NM);
            float cbp = 0.f;
            int hh = p & 1;
            float4* Ud = (float4*)(Ubuf + row * 128 + (p >> 1) * 64 + hh * 32);
            #pragma unroll
            for (int i = 0; i < 8; i++) {
                int q4 = hh * 8 + i;
                float4 mv = M4[q4];
                float4 iv = *(const float4*)(g_inv_sd + q4 * 4);
                float a = mv.x * iv.x, b = mv.y * iv.y, c = mv.z * iv.z, d = mv.w * iv.w;
                float4 qv = make_float4(a * a, b * b, c * c, d * d);
                if (p < 2) {
                    float4 sv = S4[q4];
                    float4 uv = make_float4(qv.x * sv.x, qv.y * sv.y, qv.z * sv.z, qv.w * sv.w);
                    cbp += uv.x * sv.x + uv.y * sv.y + uv.z * sv.z + uv.w * sv.w;
                    Ud[i] = uv;
                } else {
                    Ud[i] = qv;
                }
            }
            cbp += __shfl_down_sync(0xffffffffu, cbp, 1);
            if (p == 0) sCb[row] = -0.5f * cbp;
        }
        __syncthreads();

        {
            const int mt = warp & 3;
            const int ksb = (warp >> 2) * 4;
            const int rA = mt * 16 + (lane >> 2), rB = rA + 8;
            const float2* U2 = (const float2*)Ubuf;
            #pragma unroll
            for (int kk = 0; kk < 4; kk++) {
                int ks = ksb + kk;
                int k0 = ks * 16 + 2 * (lane & 3);
                float2 A0 = U2[rA * 64 + (k0 >> 1)];
                float2 A1 = U2[rB * 64 + (k0 >> 1)];
                float2 A2 = U2[rA * 64 + ((k0 + 8) >> 1)];
                float2 A3 = U2[rB * 64 + ((k0 + 8) >> 1)];
                uint32_t L0[4], L1[4];
                split2(A0, L0[0], L1[0]);
                split2(A1, L0[1], L1[1]);
                split2(A2, L0[2], L1[2]);
                split2(A3, L0[3], L1[3]);
                uint32_t off = sb + SM_A + (uint32_t)(((ks * 4 + mt) * 32 + lane) * 16);
                sts128(off,          L0[0], L0[1], L0[2], L0[3]);
                sts128(off + 16384u, L1[0], L1[1], L1[2], L1[3]);
            }
        }
        __syncthreads();

        float cbA[2], cbB[2];
        #pragma unroll
        for (int mi = 0; mi < 2; mi++) {
            cbA[mi] = sCb[wm * 32 + mi * 16 + (lane >> 2)];
            cbB[mi] = sCb[wm * 32 + mi * 16 + (lane >> 2) + 8];
        }
        float acc[2][4][4];
        #pragma unroll
        for (int mi = 0; mi < 2; mi++)
            #pragma unroll
            for (int j = 0; j < 4; j++)
                #pragma unroll
                for (int q = 0; q < 4; q++) acc[mi][j][q] = 0.f;
        float rmax[4];
        #pragma unroll
        for (int i = 0; i < 4; i++) rmax[i] = -1e30f;

        #pragma unroll 1
        for (int u = 0; u < 16; u++) {
            if (u + 1 < 16) {
                const char* src = (const char*)g_Wb + (size_t)(u + 1) * 32768 + (size_t)t * 16;
                uint32_t dst = sb + SM_B + (uint32_t)((u + 1) & 1) * 32768u + (uint32_t)t * 16;
                #pragma unroll
                for (int i = 0; i < 8; i++) cp16(dst + i * 4096, src + (size_t)i * 4096);
                asm volatile("cp.async.commit_group;" ::: "memory");
                asm volatile("cp.async.wait_group 1;" ::: "memory");
            } else {
                asm volatile("cp.async.wait_group 0;" ::: "memory");
            }
            __syncthreads();

            const uint32_t bBase = sb + SM_B + (uint32_t)(u & 1) * 32768u
                                 + (uint32_t)(((wn * 4) * 32 + lane) * 8);
            #pragma unroll
            for (int ks = 0; ks < 8; ks++) {
                uint2 bf[4];
                #pragma unroll
                for (int j = 0; j < 4; j++)
                    bf[j] = lds64(bBase + (uint32_t)((ks * 16 + j) * 256));
                #pragma unroll
                for (int lvl = 0; lvl < 2; lvl++) {
                    uint4 af0 = lds128(sb + SM_A + (uint32_t)lvl * 16384u
                                       + (uint32_t)(((ks * 4 + wm * 2) * 32 + lane) * 16));
                    uint4 af1 = lds128(sb + SM_A + (uint32_t)lvl * 16384u
                                       + (uint32_t)(((ks * 4 + wm * 2 + 1) * 32 + lane) * 16));
                    #pragma unroll
                    for (int j = 0; j < 4; j++) {
                        mma16816(acc[0][j], af0, bf[j]);
                        mma16816(acc[1][j], af1, bf[j]);
                    }
                }
            }
            __syncthreads();

            if (u & 1) {
                const int chunk = u >> 1;
                const int colBase = chunk * 128 + wn * 32 + 2 * (lane & 3);
                #pragma unroll
                for (int j = 0; j < 4; j++) {
                    const float2 lp = *(const float2*)(g_logprior + colBase + j * 8);
                    #pragma unroll
                    for (int mi = 0; mi < 2; mi++) {
                        const int rA = wm * 32 + mi * 16 + (lane >> 2);
                        float l00 = lp.x + fminf(acc[mi][j][0] + cbA[mi], 0.f);
                        float l01 = lp.y + fminf(acc[mi][j][1] + cbA[mi], 0.f);
                        float l10 = lp.x + fminf(acc[mi][j][2] + cbB[mi], 0.f);
                        float l11 = lp.y + fminf(acc[mi][j][3] + cbB[mi], 0.f);
                        rmax[mi * 2]     = fmaxf(rmax[mi * 2],     fmaxf(l00, l01));
                        rmax[mi * 2 + 1] = fmaxf(rmax[mi * 2 + 1], fmaxf(l10, l11));
                        *(float2*)(scratch + (size_t)(r0 + rA) * NN + colBase + j * 8)
                            = make_float2(l00, l01);
                        *(float2*)(scratch + (size_t)(r0 + rA + 8) * NN + colBase + j * 8)
                            = make_float2(l10, l11);
                        acc[mi][j][0] = 0.f; acc[mi][j][1] = 0.f;
                        acc[mi][j][2] = 0.f; acc[mi][j][3] = 0.f;
                    }
                }
            }
        }

        #pragma unroll
        for (int i = 0; i < 4; i++) {
            rmax[i] = fmaxf(rmax[i], __shfl_xor_sync(0xffffffffu, rmax[i], 1));
            rmax[i] = fmaxf(rmax[i], __shfl_xor_sync(0xffffffffu, rmax[i], 2));
        }
        if ((lane & 3) == 0) {
            #pragma unroll
            for (int mi = 0; mi < 2; mi++) {
                int rA = wm * 32 + mi * 16 + (lane >> 2);
                sRm[wn * 64 + rA]     = rmax[mi * 2];
                sRm[wn * 64 + rA + 8] = rmax[mi * 2 + 1];
            }
        }
        __syncthreads();
        if (t < 64) {
            float m = fmaxf(fmaxf(sRm[t], sRm[64 + t]),
                            fmaxf(sRm[128 + t], sRm[192 + t]));
            g_rowmax[r0 + t] = m;
        }
        __threadfence();
        __syncthreads();
        if (t == 0) atomicExch(&g_flag[blockIdx.x], 1);
    } else {
        // ============ softmax branch: 16 rows/block, 2 rows/warp ============
        const int sbid = blockIdx.x - NGEMM;
        const int rb = sbid >> 2;                     // producer block index
        if (t == 0) {
            while (atomicAdd(&g_flag[rb], 0) == 0) __nanosleep(256);
        }
        __syncthreads();
        __threadfence();

        const int rowA = sbid * 16 + warp * 2;
        const int rowB = rowA + 1;
        const float mxA = g_rowmax[rowA], mxB = g_rowmax[rowB];
        const float4* LA = (const float4*)(scratch + (size_t)rowA * NN);
        const float4* LB = (const float4*)(scratch + (size_t)rowB * NN);
        float4 xa[8], xb[8];
        #pragma unroll
        for (int i = 0; i < 8; i++) { xa[i] = LA[lane + 32 * i]; xb[i] = LB[lane + 32 * i]; }
        float sA = 0.f, sB = 0.f;
        #pragma unroll
        for (int i = 0; i < 8; i++) {
            float4 v = xa[i];
            float p0 = 0.f, p1 = 0.f, p2 = 0.f, p3 = 0.f;
            float d0 = v.x - mxA, d1 = v.y - mxA, d2 = v.z - mxA, d3 = v.w - mxA;
            if (d0 > -3.4f) { float e = __expf(d0); p0 = (e > 0.05f) ? e : 0.f; }
            if (d1 > -3.4f) { float e = __expf(d1); p1 = (e > 0.05f) ? e : 0.f; }
            if (d2 > -3.4f) { float e = __expf(d2); p2 = (e > 0.05f) ? e : 0.f; }
            if (d3 > -3.4f) { float e = __expf(d3); p3 = (e > 0.05f) ? e : 0.f; }
            xa[i] = make_float4(p0, p1, p2, p3);
            sA += (p0 + p1) + (p2 + p3);
            v = xb[i];
            p0 = 0.f; p1 = 0.f; p2 = 0.f; p3 = 0.f;
            d0 = v.x - mxB; d1 = v.y - mxB; d2 = v.z - mxB; d3 = v.w - mxB;
            if (d0 > -3.4f) { float e = __expf(d0); p0 = (e > 0.05f) ? e : 0.f; }
            if (d1 > -3.4f) { float e = __expf(d1); p1 = (e > 0.05f) ? e : 0.f; }
            if (d2 > -3.4f) { float e = __expf(d2); p2 = (e > 0.05f) ? e : 0.f; }
            if (d3 > -3.4f) { float e = __expf(d3); p3 = (e > 0.05f) ? e : 0.f; }
            xb[i] = make_float4(p0, p1, p2, p3);
            sB += (p0 + p1) + (p2 + p3);
        }
        #pragma unroll
        for (int o = 16; o > 0; o >>= 1) {
            sA += __shfl_xor_sync(0xffffffffu, sA, o);
            sB += __shfl_xor_sync(0xffffffffu, sB, o);
        }
        const float invA = 1.0f / sA, invB = 1.0f / sB;
        const float LZ = __logf(1e-20f);
        float4* poA = (float4*)(out + (size_t)rowA * NN);
        float4* loA = (float4*)(scratch + (size_t)rowA * NN);
        float4* poB = (float4*)(out + (size_t)rowB * NN);
        float4* loB = (float4*)(scratch + (size_t)rowB * NN);
        #pragma unroll
        for (int i = 0; i < 8; i++) {
            float4 v = xa[i];
            float4 P = make_float4(v.x * invA, v.y * invA, v.z * invA, v.w * invA);
            float4 Lg;
            Lg.x = (v.x > 0.f) ? __logf(P.x + 1e-20f) : LZ;
            Lg.y = (v.y > 0.f) ? __logf(P.y + 1e-20f) : LZ;
            Lg.z = (v.z > 0.f) ? __logf(P.z + 1e-20f) : LZ;
            Lg.w = (v.w > 0.f) ? __logf(P.w + 1e-20f) : LZ;
            poA[lane + 32 * i] = P;
            loA[lane + 32 * i] = Lg;
            v = xb[i];
            P = make_float4(v.x * invB, v.y * invB, v.z * invB, v.w * invB);
            Lg.x = (v.x > 0.f) ? __logf(P.x + 1e-20f) : LZ;
            Lg.y = (v.y > 0.f) ? __logf(P.y + 1e-20f) : LZ;
            Lg.z = (v.z > 0.f) ? __logf(P.z + 1e-20f) : LZ;
            Lg.w = (v.w > 0.f) ? __logf(P.w + 1e-20f) : LZ;
            poB[lane + 32 * i] = P;
            loB[lane + 32 * i] = Lg;
        }
    }
}

extern "C" void kernel_launch(void* const* d_in, const int* in_sizes, int n_in,
                              void* d_out, int out_size) {
    const float* samples = (const float*)d_in[0];
    const float* mask    = (const float*)d_in[1];
    const float* cent    = (const float*)d_in[2];
    const float* sd      = (const float*)d_in[3];
    const float* lm      = (const float*)d_in[4];
    float* out = (float*)d_out;
    (void)in_sizes; (void)n_in; (void)out_size;

    cudaFuncSetAttribute(fused_pipe, cudaFuncAttributeMaxDynamicSharedMemorySize, SM_TOT);

    prep_all<<<256, 256>>>(cent, sd, lm);
    fused_pipe<<<NGEMM + NSOFT, 256, SM_TOT>>>(samples, mask, out);
}